// round 15
// baseline (speedup 1.0000x reference)
#include <cuda_runtime.h>

#define Bc 32
#define Lc 128
#define Hc 100
#define Pc 20
#define HPAD 101
#define NCOL 105
#define EPSF 1e-8f
#define MINV -1e7f
#define PAD84 84

// ---------------- scratch (device globals; no allocation allowed) ----------------
__device__ float g_v[2*Bc*Lc*Hc];        // masked vectors, [side][b][i][h]
__device__ float g_vc[2*Bc*Lc*Hc];       // compacted unmasked vectors, [side][b][kk][h]
__device__ float g_vT[2*Bc*Hc*Lc];       // transposed: [side][b][h][i]
__device__ float g_rnorm[2*Bc*Lc];       // 1/max(norm, eps)
__device__ float g_maskf[2*Bc*Lc];
__device__ float g_rnw[2*Bc*Lc*Pc];      // 1/max(||w1[p]*v_i||, eps)
__device__ float g_cnt[2*Bc];
__device__ float g_maxm[2*Bc];
__device__ float g_last[2*Bc*Hc];
__device__ float g_cos[Bc*Lc*Lc];        // [b][i][j]
__device__ float g_cosT[Bc*Lc*Lc];       // [b][j][i]
__device__ float g_cmax[Bc*Lc];          // side 0 (k1)
__device__ float g_cmsum[Bc*Lc];         // side 0 (k1)
__device__ float g_cfsum[Bc*Lc];         // side 0 (k1)
__device__ int   g_icnt[2*Bc];           // unmasked token counts
__device__ int   g_ilist[2*Bc*Lc];       // compacted unmasked token indices

// ---------------- K0: prep (staging + rnw + compaction + compacted vectors) ----------------
__global__ __launch_bounds__(256) void k0_prep(const float* __restrict__ ctxp, const int* __restrict__ maskp,
                                               const float* __restrict__ ctxh, const int* __restrict__ maskh,
                                               const float* __restrict__ w1) {
    extern __shared__ float sm0[];
    float* xs   = sm0;                   // [128][101] raw context
    float* wsqT = xs + Lc*HPAD;          // [100][20]  w1^2 transposed
    float* mv   = wsqT + Hc*Pc;          // [128] mask float
    int b = blockIdx.x, s = blockIdx.y;
    int tid = threadIdx.x;
    const float* ctx = (s == 0) ? ctxp : ctxh;
    const int*   mk  = (s == 0) ? maskp : maskh;
    __shared__ int ilsm[Lc];

    for (int idx = tid; idx < Lc*Hc; idx += 256) {
        int i = idx / Hc, h = idx - i*Hc;
        xs[i*HPAD + h] = ctx[(size_t)b*Lc*Hc + idx];
    }
    for (int idx = tid; idx < Pc*Hc; idx += 256) {
        int p = idx / Hc, h = idx - p*Hc;
        float w = __ldg(&w1[idx]);
        wsqT[h*Pc + p] = w*w;
    }
    __shared__ int scnt, smax, sidx;
    if (tid == 0) { scnt = 0; smax = 0; }
    __syncthreads();
    if (tid < Lc) {
        int mi = mk[b*Lc + tid];
        mv[tid] = (float)mi;
        atomicAdd(&scnt, mi);
        atomicMax(&smax, mi);
        g_maskf[(s*Bc + b)*Lc + tid] = (float)mi;
    }
    __syncthreads();
    if (tid == 0) {
        g_cnt[s*Bc + b]  = (float)scnt;
        g_maxm[s*Bc + b] = (float)smax;
        g_icnt[s*Bc + b] = scnt;
        sidx = (scnt > 0) ? scnt - 1 : 0;
    }

    if (tid < Lc) {
        int pos = 0;
        for (int t = 0; t < tid; t++) pos += (mv[t] > 0.f) ? 1 : 0;
        if (mv[tid] > 0.f) {
            g_ilist[(s*Bc + b)*Lc + pos] = tid;
            ilsm[pos] = tid;
        }
    }

    for (int idx = tid; idx < Lc*Hc; idx += 256) {
        int i = idx / Hc, h = idx - i*Hc;
        g_v[(size_t)(s*Bc + b)*Lc*Hc + idx] = xs[i*HPAD + h] * mv[i];
    }
    for (int idx = tid; idx < Hc*Lc; idx += 256) {
        int h = idx >> 7, i = idx & 127;
        g_vT[((size_t)(s*Bc + b)*Hc + h)*Lc + i] = xs[i*HPAD + h] * mv[i];
    }
    if (tid < Lc) {
        float ssq = 0.f;
        #pragma unroll 4
        for (int h = 0; h < Hc; h++) { float t = xs[tid*HPAD + h]; ssq = fmaf(t, t, ssq); }
        g_rnorm[(s*Bc + b)*Lc + tid] = 1.0f / fmaxf(sqrtf(ssq * mv[tid]), EPSF);
    }
    __syncthreads();
    if (tid < Hc) g_last[(s*Bc + b)*Hc + tid] = xs[sidx*HPAD + tid] * mv[sidx];

    {
        int cnt = scnt;
        for (int idx = tid; idx < cnt*Hc; idx += 256) {
            int kk = idx / Hc, h = idx - kk*Hc;
            g_vc[(size_t)(s*Bc + b)*Lc*Hc + kk*Hc + h] = xs[ilsm[kk]*HPAD + h];
        }
    }

    {
        int i = tid >> 1, hp = (tid & 1) * 10;
        float acc[10];
        #pragma unroll
        for (int p = 0; p < 10; p++) acc[p] = 0.f;
        #pragma unroll 2
        for (int h = 0; h < Hc; h++) {
            float xv = xs[i*HPAD + h];
            float xq = xv * xv;
            #pragma unroll
            for (int p = 0; p < 10; p++)
                acc[p] = fmaf(wsqT[h*Pc + hp + p], xq, acc[p]);
        }
        float m = mv[i];
        #pragma unroll
        for (int p = 0; p < 10; p++)
            g_rnw[((s*Bc + b)*Lc + i)*Pc + hp + p] = 1.0f / fmaxf(sqrtf(acc[p] * m), EPSF);
    }
}

// ---------------- K1: cos matrix (+transpose) + p-side row stats + pr0 columns + masked zero-fill ----------------
__global__ void k1_cos(const float* __restrict__ w0, float* __restrict__ out) {
    extern __shared__ float sm[];
    float* ch    = sm;                  // 128*101
    float* rnh   = ch + Lc*HPAD;        // 128
    float* mh    = rnh + Lc;            // 128
    float* negj  = mh + Lc;             // 128
    float* cp    = negj + Lc;           // 8*101
    float* cs    = cp + 8*HPAD;         // 128*9 (transpose staging)
    float* lasth = cs + Lc*9;           // 104
    float* lastp = lasth + 104;         // 104
    float* w0s   = lastp + 104;         // 100*21
    int b = blockIdx.x;
    int i0 = blockIdx.y * 8;
    int tid = threadIdx.x;

    for (int idx = tid; idx < Lc*Hc; idx += 256) {
        int j = idx / Hc, h = idx - j*Hc;
        ch[j*HPAD + h] = g_v[((1*Bc + b)*Lc + j)*Hc + h];
    }
    for (int idx = tid; idx < 8*Hc; idx += 256) {
        int il = idx / Hc, h = idx - il*Hc;
        cp[il*HPAD + h] = g_v[((0*Bc + b)*Lc + i0 + il)*Hc + h];
    }
    if (tid < Lc) {
        rnh[tid] = g_rnorm[(1*Bc + b)*Lc + tid];
        float m  = g_maskf[(1*Bc + b)*Lc + tid];
        mh[tid]  = m;
        negj[tid] = (m > 0.f) ? 0.f : MINV;
    }
    if (tid < Hc) {
        lasth[tid] = g_last[(1*Bc + b)*Hc + tid];
        lastp[tid] = g_last[(0*Bc + b)*Hc + tid];
    }
    for (int idx = tid; idx < Pc*Hc; idx += 256) {
        int p = idx / Hc, h = idx - p*Hc;
        float w = __ldg(&w0[idx]);
        w0s[h*21 + p] = w*w;
    }
    __syncthreads();

    int g = tid >> 5, lane = tid & 31;
    int i = i0 + g;
    float m1v = g_maskf[(0*Bc + b)*Lc + i];

    if (m1v > 0.f) {
        float rni = g_rnorm[(0*Bc + b)*Lc + i];
        float vmax = MINV, msum = 0.f, fsum = 0.f;
        for (int jj = 0; jj < 4; jj++) {
            int j = jj*32 + lane;
            float a0=0.f, a1=0.f, a2=0.f, a3=0.f;
            #pragma unroll
            for (int h = 0; h < Hc; h += 4) {
                a0 += cp[g*HPAD + h+0] * ch[j*HPAD + h+0];
                a1 += cp[g*HPAD + h+1] * ch[j*HPAD + h+1];
                a2 += cp[g*HPAD + h+2] * ch[j*HPAD + h+2];
                a3 += cp[g*HPAD + h+3] * ch[j*HPAD + h+3];
            }
            float dot = (a0+a1)+(a2+a3);
            float c = dot * rni * rnh[j];
            g_cos[(b*Lc + i)*Lc + j] = c;
            cs[j*9 + g] = c;
            fsum += c;
            msum = fmaf(c, mh[j], msum);
            vmax = fmaxf(vmax, c + negj[j]);
        }
        #pragma unroll
        for (int o = 16; o; o >>= 1) {
            vmax = fmaxf(vmax, __shfl_xor_sync(0xffffffffu, vmax, o));
            msum += __shfl_xor_sync(0xffffffffu, msum, o);
            fsum += __shfl_xor_sync(0xffffffffu, fsum, o);
        }
        if (lane == 0) {
            g_cmax[b*Lc + i]  = vmax;
            g_cmsum[b*Lc + i] = msum;
            g_cfsum[b*Lc + i] = fsum;
        }
    } else {
        #pragma unroll
        for (int jj = 0; jj < 4; jj++) {
            int j = jj*32 + lane;
            g_cos[(b*Lc + i)*Lc + j] = 0.f;
            cs[j*9 + g] = 0.f;
        }
        if (lane == 0) {
            g_cmax[b*Lc + i]  = 0.f;
            g_cmsum[b*Lc + i] = 0.f;
            g_cfsum[b*Lc + i] = 0.f;
        }
    }
    __syncthreads();
    if (tid < Lc) {
        int j = tid;
        float4 v0, v1;
        v0.x = cs[j*9+0]; v0.y = cs[j*9+1]; v0.z = cs[j*9+2]; v0.w = cs[j*9+3];
        v1.x = cs[j*9+4]; v1.y = cs[j*9+5]; v1.z = cs[j*9+6]; v1.w = cs[j*9+7];
        float4* dst = reinterpret_cast<float4*>(&g_cosT[(b*Lc + j)*Lc + i0]);
        dst[0] = v0; dst[1] = v1;
    }

    // ---- pr0 columns (full match vs last token): cols 2 (unweighted) and 3..22 (w0) ----
    if (lane < 21) {
        float sab0=0.f, saa0=0.f, sbb0=0.f;
        float sab1=0.f, saa1=0.f, sbb1=0.f;
        #pragma unroll 4
        for (int h = 0; h < Hc; h++) {
            float w = (lane < 20) ? w0s[h*21 + lane] : 1.f;
            float a0 = cp[g*HPAD + h], b0 = lasth[h];
            float a1 = ch[i*HPAD + h], b1 = lastp[h];
            sab0 = fmaf(w, a0*b0, sab0); saa0 = fmaf(w, a0*a0, saa0); sbb0 = fmaf(w, b0*b0, sbb0);
            sab1 = fmaf(w, a1*b1, sab1); saa1 = fmaf(w, a1*a1, saa1); sbb1 = fmaf(w, b1*b1, sbb1);
        }
        int col = (lane < 20) ? 3 + lane : 2;
        out[(size_t)(b*Lc + i)*NCOL + col] =
            sab0 / (fmaxf(sqrtf(saa0), EPSF) * fmaxf(sqrtf(sbb0), EPSF));
        out[(size_t)(Bc*Lc*NCOL) + (size_t)(b*Lc + i)*NCOL + col] =
            sab1 / (fmaxf(sqrtf(saa1), EPSF) * fmaxf(sqrtf(sbb1), EPSF));

        // ---- masked-row zero fill of all remaining columns (reference values are +/-0) ----
        if (m1v <= 0.f) {
            float* orow = out + (size_t)(b*Lc + i)*NCOL;
            if (lane == 20) { orow[0]=0.f; orow[1]=0.f; orow[63]=0.f; orow[84]=0.f; }
            else { orow[23+lane]=0.f; orow[43+lane]=0.f; orow[64+lane]=0.f; orow[85+lane]=0.f; }
        }
        if (mh[i] <= 0.f) {
            float* orow = out + (size_t)(Bc*Lc*NCOL) + (size_t)(b*Lc + i)*NCOL;
            if (lane == 20) { orow[0]=0.f; orow[1]=0.f; orow[63]=0.f; orow[84]=0.f; }
            else { orow[23+lane]=0.f; orow[43+lane]=0.f; orow[64+lane]=0.f; orow[85+lane]=0.f; }
        }
    }
}

// ---------------- K3 fused: attentive vectors + all attentive cos-sims + stats cols ----------------
// grid (B, 8, 2), 256 threads, 16 compacted rows/block. Dynamic smem ~54 KB.
__global__ __launch_bounds__(256) void k3_fused(const float* __restrict__ w2,
                                                const float* __restrict__ w3,
                                                float* __restrict__ out) {
    extern __shared__ float smf[];
    float* coef  = smf;                    // [16][128]
    float* coefc = coef + 16*Lc;           // [16][128]
    float* wsq   = coefc + 16*Lc;          // [2][100][20]
    float* amn   = wsq + 2*Hc*Pc;          // [16][HPAD]
    float* amx   = amn + 16*HPAD;          // [16][HPAD]
    float* v1r   = amx + 16*HPAD;          // [16][HPAD]
    float* negk  = v1r + 16*HPAD;          // [128]
    float* mk2   = negk + Lc;              // [128]
    float* fs16  = mk2 + Lc;               // [16]
    float* cm16  = fs16 + 16;              // [16]
    float* cs16  = cm16 + 16;              // [16]
    int*   klist = (int*)(cs16 + 16);      // [128]
    int*   rlist = klist + Lc;             // [16]

    int b = blockIdx.x, s = blockIdx.z, o = 1 - s;
    int cntr = g_icnt[s*Bc + b];
    int r0c = blockIdx.y * 16;
    if (r0c >= cntr) return;
    int cntk = g_icnt[o*Bc + b];
    int tid = threadIdx.x;

    if (tid < 16) {
        int rc = r0c + tid;
        rlist[tid] = g_ilist[(s*Bc + b)*Lc + ((rc < cntr) ? rc : cntr - 1)];
    }
    if (tid >= 128 && tid < 256) {
        int t2 = tid - 128;
        float m = g_maskf[(o*Bc + b)*Lc + t2];
        mk2[t2] = m;
        negk[t2] = (m > 0.f) ? 0.f : MINV;
        klist[t2] = (t2 < cntk) ? g_ilist[(o*Bc + b)*Lc + t2] : 0;
    }
    for (int idx = tid; idx < 2*Hc*Pc; idx += 256) {
        int pr = idx / (Hc*Pc);
        int r2i = idx - pr*(Hc*Pc);
        int h = r2i / Pc, p = r2i - h*Pc;
        const float* w = (pr == 0) ? w2 : w3;
        float wv = w[p*Hc + h];
        wsq[pr*Hc*Pc + h*Pc + p] = wv*wv;
    }
    __syncthreads();   // rlist/klist ready

    const float* src = (s == 0) ? g_cos : g_cosT;
    for (int idx = tid; idx < 16*Lc; idx += 256) {
        int rl = idx >> 7, col = idx & 127;
        coef[rl*Lc + col] = src[(b*Lc + rlist[rl])*Lc + col];
    }
    for (int idx = tid; idx < 16*Hc; idx += 256) {
        int il = idx / Hc, h = idx - il*Hc;
        v1r[il*HPAD + h] = g_v[((size_t)(s*Bc + b)*Lc + rlist[il])*Hc + h];
    }
    __syncthreads();   // coef ready

    int half = tid >> 7, ht = tid & 127;

    // gather compacted coefficients (each half gathers its 8 rows)
    if (ht < cntk) {
        int k = klist[ht];
        #pragma unroll
        for (int rl = 0; rl < 8; rl++)
            coefc[(half*8 + rl)*Lc + ht] = coef[(half*8 + rl)*Lc + k];
    }

    // s==1: column stats of cos for these 16 rows (over i, masked by side-0); rows unmasked
    if (s == 1) {
        int w = tid >> 5, lane = tid & 31;
        #pragma unroll
        for (int t = 0; t < 2; t++) {
            int rl = w*2 + t;
            float v0 = coef[rl*Lc + lane],    v1 = coef[rl*Lc + lane+32];
            float v2 = coef[rl*Lc + lane+64], v3 = coef[rl*Lc + lane+96];
            float fs = (v0+v1) + (v2+v3);
            float ms = fmaf(v0, mk2[lane], fmaf(v1, mk2[lane+32],
                        fmaf(v2, mk2[lane+64], v3*mk2[lane+96])));
            float vm = fmaxf(fmaxf(v0+negk[lane], v1+negk[lane+32]),
                             fmaxf(v2+negk[lane+64], v3+negk[lane+96]));
            #pragma unroll
            for (int o2 = 16; o2; o2 >>= 1) {
                fs += __shfl_xor_sync(0xffffffffu, fs, o2);
                ms += __shfl_xor_sync(0xffffffffu, ms, o2);
                vm = fmaxf(vm, __shfl_xor_sync(0xffffffffu, vm, o2));
            }
            if (lane == 0) { fs16[rl] = fs; cs16[rl] = ms; cm16[rl] = vm; }
        }
    }
    __syncthreads();

    // attentive mean/max vectors -> smem (half 0: rows 0-7, half 1: rows 8-15)
    if (ht < Hc) {
        float acc[8], axv[8];
        #pragma unroll
        for (int rl = 0; rl < 8; rl++) { acc[rl] = 0.f; axv[rl] = MINV; }
        const float* vcbase = &g_vc[((size_t)(o*Bc + b)*Lc)*Hc + ht];
        #pragma unroll 4
        for (int kk = 0; kk < cntk; kk++) {
            float pv = __ldg(vcbase + kk*Hc);
            #pragma unroll
            for (int rl = 0; rl < 8; rl++) {
                float prod = coefc[(half*8 + rl)*Lc + kk] * pv;
                acc[rl] += prod;
                axv[rl] = fmaxf(axv[rl], prod);
            }
        }
        float maxm2 = g_maxm[o*Bc + b];  // rows unmasked: mfac = maxm2
        #pragma unroll
        for (int rl = 0; rl < 8; rl++) {
            int lr = half*8 + rl;
            float fs = (s == 1) ? fs16[lr] : g_cfsum[b*Lc + rlist[lr]];
            amn[lr*HPAD + ht] = __fdividef(acc[rl], fmaxf(fs, EPSF));
            amx[lr*HPAD + ht] = axv[rl] * maxm2;
        }
    }
    __syncthreads();

    // ---- former k5 tasks: 16 rows x 21 slots (rows all unmasked) ----
    float cnt2  = g_cnt[o*Bc + b];
    float maxm2 = g_maxm[o*Bc + b];
    for (int t = tid; t < 336; t += 256) {
        int il = t / 21, q = t - il*21;
        if (r0c + il >= cntr) continue;
        int i = rlist[il];
        float* orow = out + (size_t)s*(Bc*Lc*NCOL) + (size_t)(b*Lc + i)*NCOL;

        if (q == 0) {
            float cm = (s == 0) ? g_cmax [b*Lc + i] : cm16[il];
            float cv = (s == 0) ? g_cmsum[b*Lc + i] : cs16[il];
            orow[0] = cm * maxm2;
            orow[1] = cv / fmaxf(cnt2, EPSF);
        }

        float sab[2] = {0.f,0.f}, saa[2] = {0.f,0.f}, sbb[2] = {0.f,0.f};
        if (q == 0) {
            #pragma unroll 4
            for (int h = 0; h < Hc; h++) {
                float a  = v1r[il*HPAD + h];
                float b1 = amn[il*HPAD + h], b2 = amx[il*HPAD + h];
                float aa = a*a;
                sab[0] = fmaf(a, b1, sab[0]); sbb[0] = fmaf(b1, b1, sbb[0]);
                sab[1] = fmaf(a, b2, sab[1]); sbb[1] = fmaf(b2, b2, sbb[1]);
                saa[0] += aa;
            }
            saa[1] = saa[0];
        } else {
            int p = q - 1;
            #pragma unroll 2
            for (int h = 0; h < Hc; h++) {
                float a  = v1r[il*HPAD + h];
                float b1 = amn[il*HPAD + h], b2 = amx[il*HPAD + h];
                float w1v = wsq[h*Pc + p], w2v = wsq[Hc*Pc + h*Pc + p];
                float aa = a*a;
                sab[0] = fmaf(w1v, a*b1, sab[0]); saa[0] = fmaf(w1v, aa, saa[0]); sbb[0] = fmaf(w1v, b1*b1, sbb[0]);
                sab[1] = fmaf(w2v, a*b2, sab[1]); saa[1] = fmaf(w2v, aa, saa[1]); sbb[1] = fmaf(w2v, b2*b2, sbb[1]);
            }
        }
        #pragma unroll
        for (int pr = 0; pr < 2; pr++) {
            float val = sab[pr] / (fmaxf(sqrtf(saa[pr]), EPSF) * fmaxf(sqrtf(sbb[pr]), EPSF));
            int col = (pr == 0) ? ((q == 0) ? 63 : 64 + (q - 1))
                    :             ((q == 0) ? 84 : 85 + (q - 1));
            orow[col] = val;
        }
    }
}

// ---------------- K4: mask-compacted symmetric pairwise GEMM ----------------
__global__ __launch_bounds__(256, 3) void k4_sym(const float* __restrict__ w1,
                                                 float* __restrict__ out) {
    __shared__ float wsq[Hc];
    __shared__ int ilist[Lc], jlist[Lc];
    __shared__ float rnw1c[Lc], rnw2c[Lc];
    __shared__ float rowmax_s[Lc], rowsum_s[Lc], colmax_s[Lc], colsum_s[Lc];
    __shared__ __align__(16) float aT[50*PAD84];
    __shared__ __align__(16) float bT[50*PAD84];

    int b = blockIdx.x, p = blockIdx.y;
    int tid = threadIdx.x;
    int tx = tid & 15, ty = tid >> 4;
    int cnt1 = g_icnt[b], cnt2 = g_icnt[Bc + b];

    for (int idx = tid; idx < Hc; idx += 256) {
        float w = __ldg(&w1[p*Hc + idx]);
        wsq[idx] = w*w;
    }
    if (tid < Lc) {
        ilist[tid] = (tid < cnt1) ? g_ilist[b*Lc + tid] : 0;
        jlist[tid] = (tid < cnt2) ? g_ilist[(Bc + b)*Lc + tid] : 0;
        rowmax_s[tid] = MINV; rowsum_s[tid] = 0.f;
        colmax_s[tid] = MINV; colsum_s[tid] = 0.f;
    }
    __syncthreads();
    if (tid < Lc) {
        rnw1c[tid] = (tid < cnt1) ? g_rnw[(b*Lc + ilist[tid])*Pc + p] : 0.f;
        rnw2c[tid] = (tid < cnt2) ? g_rnw[((Bc + b)*Lc + jlist[tid])*Pc + p] : 0.f;
    }

    const float* vc0 = &g_vc[(size_t)(0*Bc + b)*Lc*Hc];
    const float* vc1 = &g_vc[(size_t)(1*Bc + b)*Lc*Hc];

    int npi = (cnt1 + 79) / 80;
    int npj = (cnt2 + 79) / 80;

    for (int pi = 0; pi < npi; pi++)
    for (int pj = 0; pj < npj; pj++) {
        float acc[5][5];
        #pragma unroll
        for (int r = 0; r < 5; r++)
            #pragma unroll
            for (int c = 0; c < 5; c++) acc[r][c] = 0.f;

        #pragma unroll 1
        for (int kc = 0; kc < 2; kc++) {
            __syncthreads();
            for (int idx = tid; idx < 50*80; idx += 256) {
                int kk = idx / 80, ii = idx - kk*80;
                int k = kc*50 + kk;
                int ic = pi*80 + ii;
                int jc = pj*80 + ii;
                aT[kk*PAD84 + ii] = (ic < cnt1 && k < Hc) ? wsq[k] * vc0[(size_t)ic*Hc + k] : 0.f;
                bT[kk*PAD84 + ii] = (jc < cnt2 && k < Hc) ? vc1[(size_t)jc*Hc + k] : 0.f;
            }
            __syncthreads();
            #pragma unroll 5
            for (int kk = 0; kk < 50; kk++) {
                float av[5], bv[5];
                #pragma unroll
                for (int r = 0; r < 5; r++) av[r] = aT[kk*PAD84 + r*16 + ty];
                #pragma unroll
                for (int c = 0; c < 5; c++) bv[c] = bT[kk*PAD84 + c*16 + tx];
                #pragma unroll
                for (int r = 0; r < 5; r++)
                    #pragma unroll
                    for (int c = 0; c < 5; c++)
                        acc[r][c] = fmaf(av[r], bv[c], acc[r][c]);
            }
        }

        float rowm[5], rows_[5], colm[5], cols_[5];
        #pragma unroll
        for (int r = 0; r < 5; r++) { rowm[r] = MINV; rows_[r] = 0.f; colm[r] = MINV; cols_[r] = 0.f; }
        #pragma unroll
        for (int r = 0; r < 5; r++) {
            int ic = pi*80 + r*16 + ty;
            bool vi = ic < cnt1;
            float r1 = vi ? rnw1c[vi ? ic : 0] : 0.f;
            float negi_ = vi ? 0.f : MINV;
            #pragma unroll
            for (int c = 0; c < 5; c++) {
                int jc = pj*80 + c*16 + tx;
                bool vj = jc < cnt2;
                float r2 = vj ? rnw2c[vj ? jc : 0] : 0.f;
                float val = acc[r][c] * r1 * r2;
                rowm[r] = fmaxf(rowm[r], val + (vj ? 0.f : MINV));
                rows_[r] += val;
                colm[c] = fmaxf(colm[c], val + negi_);
                cols_[c] += val;
            }
        }
        __syncthreads();
        #pragma unroll
        for (int r = 0; r < 5; r++) {
            int i80 = r*16 + ty;
            aT[i80*17 + tx] = rowm[r];
            bT[i80*17 + tx] = rows_[r];
        }
        __syncthreads();
        if (tid < 80) {
            int ic = pi*80 + tid;
            if (ic < cnt1) {
                float vm = MINV, vs = 0.f;
                #pragma unroll
                for (int t = 0; t < 16; t++) { vm = fmaxf(vm, aT[tid*17 + t]); vs += bT[tid*17 + t]; }
                rowmax_s[ic] = fmaxf(rowmax_s[ic], vm);
                rowsum_s[ic] += vs;
            }
        }
        __syncthreads();
        #pragma unroll
        for (int c = 0; c < 5; c++) {
            int j80 = c*16 + tx;
            aT[j80*17 + ty] = colm[c];
            bT[j80*17 + ty] = cols_[c];
        }
        __syncthreads();
        if (tid < 80) {
            int jc = pj*80 + tid;
            if (jc < cnt2) {
                float vm = MINV, vs = 0.f;
                #pragma unroll
                for (int t = 0; t < 16; t++) { vm = fmaxf(vm, aT[tid*17 + t]); vs += bT[tid*17 + t]; }
                colmax_s[jc] = fmaxf(colmax_s[jc], vm);
                colsum_s[jc] += vs;
            }
        }
        __syncthreads();
    }

    if (tid < cnt1) {
        int i = ilist[tid];
        float mm2 = g_maxm[Bc + b];
        float c2  = g_cnt[Bc + b];
        float* orow = out + (size_t)(b*Lc + i)*NCOL;
        orow[23 + p] = rowmax_s[tid] * mm2;
        orow[43 + p] = rowsum_s[tid] / fmaxf(c2, EPSF);
    }
    if (tid < cnt2) {
        int j = jlist[tid];
        float mm1 = g_maxm[b];
        float c1  = g_cnt[b];
        float* orow = out + (size_t)(Bc*Lc*NCOL) + (size_t)(b*Lc + j)*NCOL;
        orow[23 + p] = colmax_s[tid] * mm1;
        orow[43 + p] = colsum_s[tid] / fmaxf(c1, EPSF);
    }
}

// ---------------- launch (two streams: k4 overlaps k1+k3fused) ----------------
extern "C" void kernel_launch(void* const* d_in, const int* in_sizes, int n_in,
                              void* d_out, int out_size) {
    const float* ctxp  = (const float*)d_in[0];
    const int*   maskp = (const int*)  d_in[1];
    const float* ctxh  = (const float*)d_in[2];
    const int*   maskh = (const int*)  d_in[3];
    const float* w0    = (const float*)d_in[4];
    const float* w1    = (const float*)d_in[5];
    const float* w2    = (const float*)d_in[6];
    const float* w3    = (const float*)d_in[7];
    float* out = (float*)d_out;

    static cudaStream_t s2 = [](){ cudaStream_t s; cudaStreamCreateWithFlags(&s, cudaStreamNonBlocking); return s; }();
    static cudaEvent_t evF = [](){ cudaEvent_t e; cudaEventCreateWithFlags(&e, cudaEventDisableTiming); return e; }();
    static cudaEvent_t evJ = [](){ cudaEvent_t e; cudaEventCreateWithFlags(&e, cudaEventDisableTiming); return e; }();

    const int SM0 = (Lc*HPAD + Hc*Pc + Lc) * 4;
    const int SM1 = (Lc*HPAD + 3*Lc + 8*HPAD + Lc*9 + 104 + 104 + Hc*21) * 4;
    const int SM3 = (16*Lc*2 + 2*Hc*Pc + 3*16*HPAD + 2*Lc + 48) * 4 + (Lc + 16) * 4;  // ~54 KB
    cudaFuncSetAttribute(k0_prep,  cudaFuncAttributeMaxDynamicSharedMemorySize, SM0);
    cudaFuncSetAttribute(k1_cos,   cudaFuncAttributeMaxDynamicSharedMemorySize, SM1);
    cudaFuncSetAttribute(k3_fused, cudaFuncAttributeMaxDynamicSharedMemorySize, SM3);

    k0_prep<<<dim3(Bc, 2), 256, SM0>>>(ctxp, maskp, ctxh, maskh, w1);

    // fork: k4 on s2, independent of the cos-matrix chain
    cudaEventRecord(evF, 0);
    cudaStreamWaitEvent(s2, evF, 0);
    k4_sym<<<dim3(Bc, Pc), 256, 0, s2>>>(w1, out);
    cudaEventRecord(evJ, s2);

    // main chain: k1 -> fused k3 (all former k5 work included)
    k1_cos<<<dim3(Bc, 16), 256, SM1>>>(w0, out);
    k3_fused<<<dim3(Bc, 8, 2), 256, SM3>>>(w2, w3, out);

    // join k4 before graph end
    cudaStreamWaitEvent(0, evJ, 0);
}

// round 16
// speedup vs baseline: 1.0160x; 1.0160x over previous
#include <cuda_runtime.h>

#define Bc 32
#define Lc 128
#define Hc 100
#define Pc 20
#define HPAD 101
#define NCOL 105
#define EPSF 1e-8f
#define MINV -1e7f
#define PAD84 84

// ---------------- scratch (device globals; no allocation allowed) ----------------
__device__ float g_v[2*Bc*Lc*Hc];        // masked vectors, [side][b][i][h]
__device__ float g_vc[2*Bc*Lc*Hc];       // compacted unmasked vectors, [side][b][kk][h]
__device__ float g_rnorm[2*Bc*Lc];
__device__ float g_maskf[2*Bc*Lc];
__device__ float g_rnw[2*Bc*Lc*Pc];
__device__ float g_cnt[2*Bc];
__device__ float g_maxm[2*Bc];
__device__ float g_last[2*Bc*Hc];
__device__ float g_cos[Bc*Lc*Lc];        // [b][i][j]; rows for masked i NEVER written/read
__device__ float g_cosT[Bc*Lc*Lc];       // [b][j][i]; masked-i columns never written/read
__device__ float g_cmax[Bc*Lc];          // side 0, unmasked rows only
__device__ float g_cmsum[Bc*Lc];
__device__ float g_cfsum[Bc*Lc];
__device__ int   g_icnt[2*Bc];
__device__ int   g_ilist[2*Bc*Lc];
__device__ float g_vT[2*Bc*Hc*Lc];       // kept for layout compat (k0 writes, unused ok)

// ---------------- K0: prep + masked-row output zero-fill ----------------
__global__ __launch_bounds__(256) void k0_prep(const float* __restrict__ ctxp, const int* __restrict__ maskp,
                                               const float* __restrict__ ctxh, const int* __restrict__ maskh,
                                               const float* __restrict__ w1, float* __restrict__ out) {
    extern __shared__ float sm0[];
    float* xs   = sm0;                   // [128][101]
    float* wsqT = xs + Lc*HPAD;          // [100][20]
    float* mv   = wsqT + Hc*Pc;          // [128]
    int b = blockIdx.x, s = blockIdx.y;
    int tid = threadIdx.x;
    const float* ctx = (s == 0) ? ctxp : ctxh;
    const int*   mk  = (s == 0) ? maskp : maskh;
    __shared__ int ilsm[Lc];

    for (int idx = tid; idx < Lc*Hc; idx += 256) {
        int i = idx / Hc, h = idx - i*Hc;
        xs[i*HPAD + h] = ctx[(size_t)b*Lc*Hc + idx];
    }
    for (int idx = tid; idx < Pc*Hc; idx += 256) {
        int p = idx / Hc, h = idx - p*Hc;
        float w = __ldg(&w1[idx]);
        wsqT[h*Pc + p] = w*w;
    }
    __shared__ int scnt, smax, sidx;
    if (tid == 0) { scnt = 0; smax = 0; }
    __syncthreads();
    if (tid < Lc) {
        int mi = mk[b*Lc + tid];
        mv[tid] = (float)mi;
        atomicAdd(&scnt, mi);
        atomicMax(&smax, mi);
        g_maskf[(s*Bc + b)*Lc + tid] = (float)mi;
    }
    __syncthreads();
    if (tid == 0) {
        g_cnt[s*Bc + b]  = (float)scnt;
        g_maxm[s*Bc + b] = (float)smax;
        g_icnt[s*Bc + b] = scnt;
        sidx = (scnt > 0) ? scnt - 1 : 0;
    }

    if (tid < Lc) {
        int pos = 0;
        for (int t = 0; t < tid; t++) pos += (mv[t] > 0.f) ? 1 : 0;
        if (mv[tid] > 0.f) {
            g_ilist[(s*Bc + b)*Lc + pos] = tid;
            ilsm[pos] = tid;
        }
    }

    // masked rows: ALL 105 output columns are exactly 0 in the reference
    for (int idx = tid; idx < Lc*NCOL; idx += 256) {
        int i = idx / NCOL;
        if (mv[i] <= 0.f)
            out[(size_t)s*(Bc*Lc*NCOL) + (size_t)b*Lc*NCOL + idx] = 0.f;
    }

    for (int idx = tid; idx < Lc*Hc; idx += 256) {
        int i = idx / Hc, h = idx - i*Hc;
        g_v[(size_t)(s*Bc + b)*Lc*Hc + idx] = xs[i*HPAD + h] * mv[i];
    }
    if (tid < Lc) {
        float ssq = 0.f;
        #pragma unroll 4
        for (int h = 0; h < Hc; h++) { float t = xs[tid*HPAD + h]; ssq = fmaf(t, t, ssq); }
        g_rnorm[(s*Bc + b)*Lc + tid] = 1.0f / fmaxf(sqrtf(ssq * mv[tid]), EPSF);
    }
    __syncthreads();
    if (tid < Hc) g_last[(s*Bc + b)*Hc + tid] = xs[sidx*HPAD + tid] * mv[sidx];

    {
        int cnt = scnt;
        for (int idx = tid; idx < cnt*Hc; idx += 256) {
            int kk = idx / Hc, h = idx - kk*Hc;
            g_vc[(size_t)(s*Bc + b)*Lc*Hc + kk*Hc + h] = xs[ilsm[kk]*HPAD + h];
        }
    }

    {
        int i = tid >> 1, hp = (tid & 1) * 10;
        float acc[10];
        #pragma unroll
        for (int p = 0; p < 10; p++) acc[p] = 0.f;
        #pragma unroll 2
        for (int h = 0; h < Hc; h++) {
            float xv = xs[i*HPAD + h];
            float xq = xv * xv;
            #pragma unroll
            for (int p = 0; p < 10; p++)
                acc[p] = fmaf(wsqT[h*Pc + hp + p], xq, acc[p]);
        }
        float m = mv[i];
        #pragma unroll
        for (int p = 0; p < 10; p++)
            g_rnw[((s*Bc + b)*Lc + i)*Pc + hp + p] = 1.0f / fmaxf(sqrtf(acc[p] * m), EPSF);
    }
}

// ---------------- K1: compacted cos rows (+scatter transpose) + stats + pr0 both sides ----------------
// grid (Bc, 16), 256 threads; 8 compacted side-0 rows + 8 compacted side-1 rows per block.
__global__ void k1_cos(const float* __restrict__ w0, float* __restrict__ out) {
    extern __shared__ float sm[];
    float* ch    = sm;                  // 128*101 (all side-1 rows)
    float* rnh   = ch + Lc*HPAD;        // 128
    float* negj  = rnh + Lc;            // 128
    float* cp    = negj + Lc;           // 8*101 (compacted side-0 rows)
    float* cs    = cp + 8*HPAD;         // 128*9
    float* lasth = cs + Lc*9;           // 104
    float* lastp = lasth + 104;         // 104
    float* w0s   = lastp + 104;         // 100*21
    __shared__ int rl0[8], rl1[8];

    int b = blockIdx.x;
    int r0c = blockIdx.y * 8;
    int cnt1 = g_icnt[b], cnt2 = g_icnt[Bc + b];
    if (r0c >= cnt1 && r0c >= cnt2) return;
    int tid = threadIdx.x;

    if (tid < 8) {
        int rc = r0c + tid;
        rl0[tid] = (cnt1 > 0) ? g_ilist[b*Lc + ((rc < cnt1) ? rc : cnt1 - 1)] : 0;
        rl1[tid] = (cnt2 > 0) ? g_ilist[(Bc + b)*Lc + ((rc < cnt2) ? rc : cnt2 - 1)] : 0;
    }
    for (int idx = tid; idx < Lc*Hc; idx += 256) {
        int j = idx / Hc, h = idx - j*Hc;
        ch[j*HPAD + h] = g_v[((1*Bc + b)*Lc + j)*Hc + h];
    }
    if (tid < Lc) {
        rnh[tid] = g_rnorm[(1*Bc + b)*Lc + tid];
        float m  = g_maskf[(1*Bc + b)*Lc + tid];
        negj[tid] = (m > 0.f) ? 0.f : MINV;
    }
    if (tid < Hc) {
        lasth[tid] = g_last[(1*Bc + b)*Hc + tid];
        lastp[tid] = g_last[(0*Bc + b)*Hc + tid];
    }
    for (int idx = tid; idx < Pc*Hc; idx += 256) {
        int p = idx / Hc, h = idx - p*Hc;
        float w = __ldg(&w0[idx]);
        w0s[h*21 + p] = w*w;
    }
    __syncthreads();
    for (int idx = tid; idx < 8*Hc; idx += 256) {
        int il = idx / Hc, h = idx - il*Hc;
        cp[il*HPAD + h] = g_v[((0*Bc + b)*Lc + rl0[il])*Hc + h];
    }
    __syncthreads();

    int g = tid >> 5, lane = tid & 31;
    bool act0 = (r0c + g) < cnt1;
    bool act1 = (r0c + g) < cnt2;
    int i0r = rl0[g], i1r = rl1[g];

    if (act0) {
        float rni = g_rnorm[(0*Bc + b)*Lc + i0r];
        float vmax = MINV, fsum = 0.f;
        for (int jj = 0; jj < 4; jj++) {
            int j = jj*32 + lane;
            float a0=0.f, a1=0.f, a2=0.f, a3=0.f;
            #pragma unroll
            for (int h = 0; h < Hc; h += 4) {
                a0 += cp[g*HPAD + h+0] * ch[j*HPAD + h+0];
                a1 += cp[g*HPAD + h+1] * ch[j*HPAD + h+1];
                a2 += cp[g*HPAD + h+2] * ch[j*HPAD + h+2];
                a3 += cp[g*HPAD + h+3] * ch[j*HPAD + h+3];
            }
            float dot = (a0+a1)+(a2+a3);
            float c = dot * rni * rnh[j];
            g_cos[(b*Lc + i0r)*Lc + j] = c;
            cs[j*9 + g] = c;
            fsum += c;                       // masked-j c is exactly 0 -> fsum == masked sum
            vmax = fmaxf(vmax, c + negj[j]);
        }
        #pragma unroll
        for (int o = 16; o; o >>= 1) {
            vmax = fmaxf(vmax, __shfl_xor_sync(0xffffffffu, vmax, o));
            fsum += __shfl_xor_sync(0xffffffffu, fsum, o);
        }
        if (lane == 0) {
            g_cmax[b*Lc + i0r]  = vmax;
            g_cmsum[b*Lc + i0r] = fsum;
            g_cfsum[b*Lc + i0r] = fsum;
        }
    }
    __syncthreads();
    if (tid < Lc) {
        int j = tid;
        #pragma unroll
        for (int gg = 0; gg < 8; gg++)
            if (r0c + gg < cnt1)
                g_cosT[(b*Lc + j)*Lc + rl0[gg]] = cs[j*9 + gg];
    }

    // ---- pr0 columns: cols 2 (unweighted) and 3..22 (w0), both sides ----
    if (lane < 21) {
        float sab0=0.f, saa0=0.f, sbb0=0.f;
        float sab1=0.f, saa1=0.f, sbb1=0.f;
        #pragma unroll 4
        for (int h = 0; h < Hc; h++) {
            float w = (lane < 20) ? w0s[h*21 + lane] : 1.f;
            float a0 = cp[g*HPAD + h],  b0 = lasth[h];
            float a1 = ch[i1r*HPAD + h], b1 = lastp[h];
            sab0 = fmaf(w, a0*b0, sab0); saa0 = fmaf(w, a0*a0, saa0); sbb0 = fmaf(w, b0*b0, sbb0);
            sab1 = fmaf(w, a1*b1, sab1); saa1 = fmaf(w, a1*a1, saa1); sbb1 = fmaf(w, b1*b1, sbb1);
        }
        int col = (lane < 20) ? 3 + lane : 2;
        if (act0)
            out[(size_t)(b*Lc + i0r)*NCOL + col] =
                sab0 / (fmaxf(sqrtf(saa0), EPSF) * fmaxf(sqrtf(sbb0), EPSF));
        if (act1)
            out[(size_t)(Bc*Lc*NCOL) + (size_t)(b*Lc + i1r)*NCOL + col] =
                sab1 / (fmaxf(sqrtf(saa1), EPSF) * fmaxf(sqrtf(sbb1), EPSF));
    }
}

// ---------------- K3 fused: attentive vectors + attentive cos-sims + stats cols ----------------
// grid (B, 8, 2), 256 threads, 16 compacted rows/block.
__global__ __launch_bounds__(256) void k3_fused(const float* __restrict__ w2,
                                                const float* __restrict__ w3,
                                                float* __restrict__ out) {
    extern __shared__ float smf[];
    float* coef  = smf;                    // [16][128]
    float* coefc = coef + 16*Lc;           // [16][128] (tail zeroed)
    float* wsq   = coefc + 16*Lc;          // [2][100][20]
    float* amn   = wsq + 2*Hc*Pc;          // [16][HPAD]
    float* amx   = amn + 16*HPAD;          // [16][HPAD]
    float* v1r   = amx + 16*HPAD;          // [16][HPAD]
    float* fs16  = v1r + 16*HPAD;          // [16]
    float* cm16  = fs16 + 16;              // [16]
    int*   klist = (int*)(cm16 + 16);      // [128]
    int*   rlist = klist + Lc;             // [16]

    int b = blockIdx.x, s = blockIdx.z, o = 1 - s;
    int cntr = g_icnt[s*Bc + b];
    int r0c = blockIdx.y * 16;
    if (r0c >= cntr) return;
    int cntk = g_icnt[o*Bc + b];
    int tid = threadIdx.x;

    if (tid < 16) {
        int rc = r0c + tid;
        rlist[tid] = g_ilist[(s*Bc + b)*Lc + ((rc < cntr) ? rc : cntr - 1)];
    }
    if (tid >= 128 && tid < 256) {
        int t2 = tid - 128;
        klist[t2] = (t2 < cntk) ? g_ilist[(o*Bc + b)*Lc + t2] : 0;
    }
    for (int idx = tid; idx < 2*Hc*Pc; idx += 256) {
        int pr = idx / (Hc*Pc);
        int r2i = idx - pr*(Hc*Pc);
        int h = r2i / Pc, p = r2i - h*Pc;
        const float* w = (pr == 0) ? w2 : w3;
        float wv = w[p*Hc + h];
        wsq[pr*Hc*Pc + h*Pc + p] = wv*wv;
    }
    __syncthreads();

    const float* src = (s == 0) ? g_cos : g_cosT;
    for (int idx = tid; idx < 16*Lc; idx += 256) {
        int rl = idx >> 7, col = idx & 127;
        coef[rl*Lc + col] = src[(b*Lc + rlist[rl])*Lc + col];
    }
    for (int idx = tid; idx < 16*Hc; idx += 256) {
        int il = idx / Hc, h = idx - il*Hc;
        v1r[il*HPAD + h] = g_v[((size_t)(s*Bc + b)*Lc + rlist[il])*Hc + h];
    }
    __syncthreads();

    int half = tid >> 7, ht = tid & 127;

    // gather compacted coefficients; zero the tail
    if (ht < cntk) {
        int k = klist[ht];
        #pragma unroll
        for (int rl = 0; rl < 8; rl++)
            coefc[(half*8 + rl)*Lc + ht] = coef[(half*8 + rl)*Lc + k];
    } else {
        #pragma unroll
        for (int rl = 0; rl < 8; rl++)
            coefc[(half*8 + rl)*Lc + ht] = 0.f;
    }
    __syncthreads();

    // s==1: stats from coefc (all-unmasked; fs == masked sum since masked cos entries are 0)
    if (s == 1) {
        int w = tid >> 5, lane = tid & 31;
        #pragma unroll
        for (int t = 0; t < 2; t++) {
            int rl = w*2 + t;
            float v0 = coefc[rl*Lc + lane],    v1 = coefc[rl*Lc + lane+32];
            float v2 = coefc[rl*Lc + lane+64], v3 = coefc[rl*Lc + lane+96];
            float fs = (v0+v1) + (v2+v3);
            float vm = fmaxf(fmaxf((lane      < cntk) ? v0 : MINV,
                                   (lane+32   < cntk) ? v1 : MINV),
                             fmaxf((lane+64   < cntk) ? v2 : MINV,
                                   (lane+96   < cntk) ? v3 : MINV));
            #pragma unroll
            for (int o2 = 16; o2; o2 >>= 1) {
                fs += __shfl_xor_sync(0xffffffffu, fs, o2);
                vm = fmaxf(vm, __shfl_xor_sync(0xffffffffu, vm, o2));
            }
            if (lane == 0) { fs16[rl] = fs; cm16[rl] = vm; }
        }
        __syncthreads();
    }

    // attentive mean/max vectors -> smem
    if (ht < Hc) {
        float acc[8], axv[8];
        #pragma unroll
        for (int rl = 0; rl < 8; rl++) { acc[rl] = 0.f; axv[rl] = MINV; }
        const float* vcbase = &g_vc[((size_t)(o*Bc + b)*Lc)*Hc + ht];
        #pragma unroll 4
        for (int kk = 0; kk < cntk; kk++) {
            float pv = __ldg(vcbase + kk*Hc);
            #pragma unroll
            for (int rl = 0; rl < 8; rl++) {
                float prod = coefc[(half*8 + rl)*Lc + kk] * pv;
                acc[rl] += prod;
                axv[rl] = fmaxf(axv[rl], prod);
            }
        }
        float maxm2 = g_maxm[o*Bc + b];
        #pragma unroll
        for (int rl = 0; rl < 8; rl++) {
            int lr = half*8 + rl;
            float fs = (s == 1) ? fs16[lr] : g_cfsum[b*Lc + rlist[lr]];
            amn[lr*HPAD + ht] = __fdividef(acc[rl], fmaxf(fs, EPSF));
            amx[lr*HPAD + ht] = axv[rl] * maxm2;
        }
    }
    __syncthreads();

    // ---- former k5 tasks: il = t&15, q = t>>4 (uniform q per warp except warp 0) ----
    float cnt2  = g_cnt[o*Bc + b];
    float maxm2 = g_maxm[o*Bc + b];
    for (int t = tid; t < 336; t += 256) {
        int il = t & 15, q = t >> 4;
        if (r0c + il >= cntr) continue;
        int i = rlist[il];
        float* orow = out + (size_t)s*(Bc*Lc*NCOL) + (size_t)(b*Lc + i)*NCOL;

        if (q == 0) {
            float cm = (s == 0) ? g_cmax [b*Lc + i] : cm16[il];
            float cv = (s == 0) ? g_cmsum[b*Lc + i] : fs16[il];
            orow[0] = cm * maxm2;
            orow[1] = cv / fmaxf(cnt2, EPSF);
        }

        float sab[2] = {0.f,0.f}, saa[2] = {0.f,0.f}, sbb[2] = {0.f,0.f};
        if (q == 0) {
            #pragma unroll 4
            for (int h = 0; h < Hc; h++) {
                float a  = v1r[il*HPAD + h];
                float b1 = amn[il*HPAD + h], b2 = amx[il*HPAD + h];
                float aa = a*a;
                sab[0] = fmaf(a, b1, sab[0]); sbb[0] = fmaf(b1, b1, sbb[0]);
                sab[1] = fmaf(a, b2, sab[1]); sbb[1] = fmaf(b2, b2, sbb[1]);
                saa[0] += aa;
            }
            saa[1] = saa[0];
        } else {
            int p = q - 1;
            #pragma unroll 2
            for (int h = 0; h < Hc; h++) {
                float a  = v1r[il*HPAD + h];
                float b1 = amn[il*HPAD + h], b2 = amx[il*HPAD + h];
                float w1v = wsq[h*Pc + p], w2v = wsq[Hc*Pc + h*Pc + p];
                float aa = a*a;
                sab[0] = fmaf(w1v, a*b1, sab[0]); saa[0] = fmaf(w1v, aa, saa[0]); sbb[0] = fmaf(w1v, b1*b1, sbb[0]);
                sab[1] = fmaf(w2v, a*b2, sab[1]); saa[1] = fmaf(w2v, aa, saa[1]); sbb[1] = fmaf(w2v, b2*b2, sbb[1]);
            }
        }
        #pragma unroll
        for (int pr = 0; pr < 2; pr++) {
            float val = sab[pr] / (fmaxf(sqrtf(saa[pr]), EPSF) * fmaxf(sqrtf(sbb[pr]), EPSF));
            int col = (pr == 0) ? ((q == 0) ? 63 : 64 + (q - 1))
                    :             ((q == 0) ? 84 : 85 + (q - 1));
            orow[col] = val;
        }
    }
}

// ---------------- K4: mask-compacted symmetric pairwise GEMM ----------------
__global__ __launch_bounds__(256, 3) void k4_sym(const float* __restrict__ w1,
                                                 float* __restrict__ out) {
    __shared__ float wsq[Hc];
    __shared__ int ilist[Lc], jlist[Lc];
    __shared__ float rnw1c[Lc], rnw2c[Lc];
    __shared__ float rowmax_s[Lc], rowsum_s[Lc], colmax_s[Lc], colsum_s[Lc];
    __shared__ __align__(16) float aT[50*PAD84];
    __shared__ __align__(16) float bT[50*PAD84];

    int b = blockIdx.x, p = blockIdx.y;
    int tid = threadIdx.x;
    int tx = tid & 15, ty = tid >> 4;
    int cnt1 = g_icnt[b], cnt2 = g_icnt[Bc + b];

    for (int idx = tid; idx < Hc; idx += 256) {
        float w = __ldg(&w1[p*Hc + idx]);
        wsq[idx] = w*w;
    }
    if (tid < Lc) {
        ilist[tid] = (tid < cnt1) ? g_ilist[b*Lc + tid] : 0;
        jlist[tid] = (tid < cnt2) ? g_ilist[(Bc + b)*Lc + tid] : 0;
        rowmax_s[tid] = MINV; rowsum_s[tid] = 0.f;
        colmax_s[tid] = MINV; colsum_s[tid] = 0.f;
    }
    __syncthreads();
    if (tid < Lc) {
        rnw1c[tid] = (tid < cnt1) ? g_rnw[(b*Lc + ilist[tid])*Pc + p] : 0.f;
        rnw2c[tid] = (tid < cnt2) ? g_rnw[((Bc + b)*Lc + jlist[tid])*Pc + p] : 0.f;
    }

    const float* vc0 = &g_vc[(size_t)(0*Bc + b)*Lc*Hc];
    const float* vc1 = &g_vc[(size_t)(1*Bc + b)*Lc*Hc];

    int npi = (cnt1 + 79) / 80;
    int npj = (cnt2 + 79) / 80;

    for (int pi = 0; pi < npi; pi++)
    for (int pj = 0; pj < npj; pj++) {
        float acc[5][5];
        #pragma unroll
        for (int r = 0; r < 5; r++)
            #pragma unroll
            for (int c = 0; c < 5; c++) acc[r][c] = 0.f;

        #pragma unroll 1
        for (int kc = 0; kc < 2; kc++) {
            __syncthreads();
            for (int idx = tid; idx < 50*80; idx += 256) {
                int kk = idx / 80, ii = idx - kk*80;
                int k = kc*50 + kk;
                int ic = pi*80 + ii;
                int jc = pj*80 + ii;
                aT[kk*PAD84 + ii] = (ic < cnt1 && k < Hc) ? wsq[k] * vc0[(size_t)ic*Hc + k] : 0.f;
                bT[kk*PAD84 + ii] = (jc < cnt2 && k < Hc) ? vc1[(size_t)jc*Hc + k] : 0.f;
            }
            __syncthreads();
            #pragma unroll 5
            for (int kk = 0; kk < 50; kk++) {
                float av[5], bv[5];
                #pragma unroll
                for (int r = 0; r < 5; r++) av[r] = aT[kk*PAD84 + r*16 + ty];
                #pragma unroll
                for (int c = 0; c < 5; c++) bv[c] = bT[kk*PAD84 + c*16 + tx];
                #pragma unroll
                for (int r = 0; r < 5; r++)
                    #pragma unroll
                    for (int c = 0; c < 5; c++)
                        acc[r][c] = fmaf(av[r], bv[c], acc[r][c]);
            }
        }

        float rowm[5], rows_[5], colm[5], cols_[5];
        #pragma unroll
        for (int r = 0; r < 5; r++) { rowm[r] = MINV; rows_[r] = 0.f; colm[r] = MINV; cols_[r] = 0.f; }
        #pragma unroll
        for (int r = 0; r < 5; r++) {
            int ic = pi*80 + r*16 + ty;
            bool vi = ic < cnt1;
            float r1 = vi ? rnw1c[vi ? ic : 0] : 0.f;
            float negi_ = vi ? 0.f : MINV;
            #pragma unroll
            for (int c = 0; c < 5; c++) {
                int jc = pj*80 + c*16 + tx;
                bool vj = jc < cnt2;
                float r2 = vj ? rnw2c[vj ? jc : 0] : 0.f;
                float val = acc[r][c] * r1 * r2;
                rowm[r] = fmaxf(rowm[r], val + (vj ? 0.f : MINV));
                rows_[r] += val;
                colm[c] = fmaxf(colm[c], val + negi_);
                cols_[c] += val;
            }
        }
        __syncthreads();
        #pragma unroll
        for (int r = 0; r < 5; r++) {
            int i80 = r*16 + ty;
            aT[i80*17 + tx] = rowm[r];
            bT[i80*17 + tx] = rows_[r];
        }
        __syncthreads();
        if (tid < 80) {
            int ic = pi*80 + tid;
            if (ic < cnt1) {
                float vm = MINV, vs = 0.f;
                #pragma unroll
                for (int t = 0; t < 16; t++) { vm = fmaxf(vm, aT[tid*17 + t]); vs += bT[tid*17 + t]; }
                rowmax_s[ic] = fmaxf(rowmax_s[ic], vm);
                rowsum_s[ic] += vs;
            }
        }
        __syncthreads();
        #pragma unroll
        for (int c = 0; c < 5; c++) {
            int j80 = c*16 + tx;
            aT[j80*17 + ty] = colm[c];
            bT[j80*17 + ty] = cols_[c];
        }
        __syncthreads();
        if (tid < 80) {
            int jc = pj*80 + tid;
            if (jc < cnt2) {
                float vm = MINV, vs = 0.f;
                #pragma unroll
                for (int t = 0; t < 16; t++) { vm = fmaxf(vm, aT[tid*17 + t]); vs += bT[tid*17 + t]; }
                colmax_s[jc] = fmaxf(colmax_s[jc], vm);
                colsum_s[jc] += vs;
            }
        }
        __syncthreads();
    }

    if (tid < cnt1) {
        int i = ilist[tid];
        float mm2 = g_maxm[Bc + b];
        float c2  = g_cnt[Bc + b];
        float* orow = out + (size_t)(b*Lc + i)*NCOL;
        orow[23 + p] = rowmax_s[tid] * mm2;
        orow[43 + p] = rowsum_s[tid] / fmaxf(c2, EPSF);
    }
    if (tid < cnt2) {
        int j = jlist[tid];
        float mm1 = g_maxm[b];
        float c1  = g_cnt[b];
        float* orow = out + (size_t)(Bc*Lc*NCOL) + (size_t)(b*Lc + j)*NCOL;
        orow[23 + p] = colmax_s[tid] * mm1;
        orow[43 + p] = colsum_s[tid] / fmaxf(c1, EPSF);
    }
}

// ---------------- launch (two streams: k4 overlaps k1+k3fused) ----------------
extern "C" void kernel_launch(void* const* d_in, const int* in_sizes, int n_in,
                              void* d_out, int out_size) {
    const float* ctxp  = (const float*)d_in[0];
    const int*   maskp = (const int*)  d_in[1];
    const float* ctxh  = (const float*)d_in[2];
    const int*   maskh = (const int*)  d_in[3];
    const float* w0    = (const float*)d_in[4];
    const float* w1    = (const float*)d_in[5];
    const float* w2    = (const float*)d_in[6];
    const float* w3    = (const float*)d_in[7];
    float* out = (float*)d_out;

    static cudaStream_t s2 = [](){ cudaStream_t s; cudaStreamCreateWithFlags(&s, cudaStreamNonBlocking); return s; }();
    static cudaEvent_t evF = [](){ cudaEvent_t e; cudaEventCreateWithFlags(&e, cudaEventDisableTiming); return e; }();
    static cudaEvent_t evJ = [](){ cudaEvent_t e; cudaEventCreateWithFlags(&e, cudaEventDisableTiming); return e; }();

    const int SM0 = (Lc*HPAD + Hc*Pc + Lc) * 4;
    const int SM1 = (Lc*HPAD + 2*Lc + 8*HPAD + Lc*9 + 104 + 104 + Hc*21) * 4;
    const int SM3 = (16*Lc*2 + 2*Hc*Pc + 3*16*HPAD + 32) * 4 + (Lc + 16) * 4;
    cudaFuncSetAttribute(k0_prep,  cudaFuncAttributeMaxDynamicSharedMemorySize, SM0);
    cudaFuncSetAttribute(k1_cos,   cudaFuncAttributeMaxDynamicSharedMemorySize, SM1);
    cudaFuncSetAttribute(k3_fused, cudaFuncAttributeMaxDynamicSharedMemorySize, SM3);

    k0_prep<<<dim3(Bc, 2), 256, SM0>>>(ctxp, maskp, ctxh, maskh, w1, out);

    cudaEventRecord(evF, 0);
    cudaStreamWaitEvent(s2, evF, 0);
    k4_sym<<<dim3(Bc, Pc), 256, 0, s2>>>(w1, out);
    cudaEventRecord(evJ, s2);

    k1_cos<<<dim3(Bc, 16), 256, SM1>>>(w0, out);
    k3_fused<<<dim3(Bc, 8, 2), 256, SM3>>>(w2, w3, out);

    cudaStreamWaitEvent(0, evJ, 0);
}

// round 17
// speedup vs baseline: 1.1146x; 1.0970x over previous
#include <cuda_runtime.h>

#define Bc 32
#define Lc 128
#define Hc 100
#define Pc 20
#define HPAD 101
#define NCOL 105
#define EPSF 1e-8f
#define MINV -1e7f
#define PAD84 84

// ---------------- scratch (device globals; no allocation allowed) ----------------
__device__ float g_v[2*Bc*Lc*Hc];        // masked vectors, [side][b][i][h]
__device__ float g_vc[2*Bc*Lc*Hc];       // compacted unmasked vectors, [side][b][kk][h]
__device__ float g_rnorm[2*Bc*Lc];
__device__ float g_maskf[2*Bc*Lc];
__device__ float g_rnw[2*Bc*Lc*Pc];
__device__ float g_cnt[2*Bc];
__device__ float g_maxm[2*Bc];
__device__ float g_last[2*Bc*Hc];
__device__ float g_cos[Bc*Lc*Lc];        // [b][i][j]; masked-i rows never written/read
__device__ float g_cosT[Bc*Lc*Lc];       // [b][j][i]; masked-i columns never written/read
__device__ float g_cmax[Bc*Lc];          // side 0, unmasked rows only
__device__ float g_cmsum[Bc*Lc];
__device__ float g_cfsum[Bc*Lc];
__device__ int   g_icnt[2*Bc];
__device__ int   g_ilist[2*Bc*Lc];

// ---------------- K0: prep + masked-row output zero-fill ----------------
__global__ __launch_bounds__(256) void k0_prep(const float* __restrict__ ctxp, const int* __restrict__ maskp,
                                               const float* __restrict__ ctxh, const int* __restrict__ maskh,
                                               const float* __restrict__ w1, float* __restrict__ out) {
    extern __shared__ float sm0[];
    float* xs   = sm0;                   // [128][101]
    float* wsqT = xs + Lc*HPAD;          // [100][20]
    float* mv   = wsqT + Hc*Pc;          // [128]
    int b = blockIdx.x, s = blockIdx.y;
    int tid = threadIdx.x;
    const float* ctx = (s == 0) ? ctxp : ctxh;
    const int*   mk  = (s == 0) ? maskp : maskh;
    __shared__ int ilsm[Lc];

    for (int idx = tid; idx < Lc*Hc; idx += 256) {
        int i = idx / Hc, h = idx - i*Hc;
        xs[i*HPAD + h] = ctx[(size_t)b*Lc*Hc + idx];
    }
    for (int idx = tid; idx < Pc*Hc; idx += 256) {
        int p = idx / Hc, h = idx - p*Hc;
        float w = __ldg(&w1[idx]);
        wsqT[h*Pc + p] = w*w;
    }
    __shared__ int scnt, smax, sidx;
    if (tid == 0) { scnt = 0; smax = 0; }
    __syncthreads();
    if (tid < Lc) {
        int mi = mk[b*Lc + tid];
        mv[tid] = (float)mi;
        atomicAdd(&scnt, mi);
        atomicMax(&smax, mi);
        g_maskf[(s*Bc + b)*Lc + tid] = (float)mi;
    }
    __syncthreads();
    if (tid == 0) {
        g_cnt[s*Bc + b]  = (float)scnt;
        g_maxm[s*Bc + b] = (float)smax;
        g_icnt[s*Bc + b] = scnt;
        sidx = (scnt > 0) ? scnt - 1 : 0;
    }

    if (tid < Lc) {
        int pos = 0;
        for (int t = 0; t < tid; t++) pos += (mv[t] > 0.f) ? 1 : 0;
        if (mv[tid] > 0.f) {
            g_ilist[(s*Bc + b)*Lc + pos] = tid;
            ilsm[pos] = tid;
        }
    }

    // masked rows: ALL 105 output columns are exactly 0 in the reference
    for (int idx = tid; idx < Lc*NCOL; idx += 256) {
        int i = idx / NCOL;
        if (mv[i] <= 0.f)
            out[(size_t)s*(Bc*Lc*NCOL) + (size_t)b*Lc*NCOL + idx] = 0.f;
    }

    for (int idx = tid; idx < Lc*Hc; idx += 256) {
        int i = idx / Hc, h = idx - i*Hc;
        g_v[(size_t)(s*Bc + b)*Lc*Hc + idx] = xs[i*HPAD + h] * mv[i];
    }
    if (tid < Lc) {
        float ssq = 0.f;
        #pragma unroll 4
        for (int h = 0; h < Hc; h++) { float t = xs[tid*HPAD + h]; ssq = fmaf(t, t, ssq); }
        g_rnorm[(s*Bc + b)*Lc + tid] = 1.0f / fmaxf(sqrtf(ssq * mv[tid]), EPSF);
    }
    __syncthreads();
    if (tid < Hc) g_last[(s*Bc + b)*Hc + tid] = xs[sidx*HPAD + tid] * mv[sidx];

    {
        int cnt = scnt;
        for (int idx = tid; idx < cnt*Hc; idx += 256) {
            int kk = idx / Hc, h = idx - kk*Hc;
            g_vc[(size_t)(s*Bc + b)*Lc*Hc + kk*Hc + h] = xs[ilsm[kk]*HPAD + h];
        }
    }

    {
        int i = tid >> 1, hp = (tid & 1) * 10;
        float acc[10];
        #pragma unroll
        for (int p = 0; p < 10; p++) acc[p] = 0.f;
        #pragma unroll 2
        for (int h = 0; h < Hc; h++) {
            float xv = xs[i*HPAD + h];
            float xq = xv * xv;
            #pragma unroll
            for (int p = 0; p < 10; p++)
                acc[p] = fmaf(wsqT[h*Pc + hp + p], xq, acc[p]);
        }
        float m = mv[i];
        #pragma unroll
        for (int p = 0; p < 10; p++)
            g_rnw[((s*Bc + b)*Lc + i)*Pc + hp + p] = 1.0f / fmaxf(sqrtf(acc[p] * m), EPSF);
    }
}

// ---------------- K1: compacted cos rows (+scatter transpose) + stats + pr0 both sides ----------------
__global__ void k1_cos(const float* __restrict__ w0, float* __restrict__ out) {
    extern __shared__ float sm[];
    float* ch    = sm;                  // 128*101
    float* rnh   = ch + Lc*HPAD;        // 128
    float* negj  = rnh + Lc;            // 128
    float* cp    = negj + Lc;           // 8*101
    float* cs    = cp + 8*HPAD;         // 128*9
    float* lasth = cs + Lc*9;           // 104
    float* lastp = lasth + 104;         // 104
    float* w0s   = lastp + 104;         // 100*21
    __shared__ int rl0[8], rl1[8];

    int b = blockIdx.x;
    int r0c = blockIdx.y * 8;
    int cnt1 = g_icnt[b], cnt2 = g_icnt[Bc + b];
    if (r0c >= cnt1 && r0c >= cnt2) return;
    int tid = threadIdx.x;

    if (tid < 8) {
        int rc = r0c + tid;
        rl0[tid] = (cnt1 > 0) ? g_ilist[b*Lc + ((rc < cnt1) ? rc : cnt1 - 1)] : 0;
        rl1[tid] = (cnt2 > 0) ? g_ilist[(Bc + b)*Lc + ((rc < cnt2) ? rc : cnt2 - 1)] : 0;
    }
    for (int idx = tid; idx < Lc*Hc; idx += 256) {
        int j = idx / Hc, h = idx - j*Hc;
        ch[j*HPAD + h] = g_v[((1*Bc + b)*Lc + j)*Hc + h];
    }
    if (tid < Lc) {
        rnh[tid] = g_rnorm[(1*Bc + b)*Lc + tid];
        float m  = g_maskf[(1*Bc + b)*Lc + tid];
        negj[tid] = (m > 0.f) ? 0.f : MINV;
    }
    if (tid < Hc) {
        lasth[tid] = g_last[(1*Bc + b)*Hc + tid];
        lastp[tid] = g_last[(0*Bc + b)*Hc + tid];
    }
    for (int idx = tid; idx < Pc*Hc; idx += 256) {
        int p = idx / Hc, h = idx - p*Hc;
        float w = __ldg(&w0[idx]);
        w0s[h*21 + p] = w*w;
    }
    __syncthreads();
    for (int idx = tid; idx < 8*Hc; idx += 256) {
        int il = idx / Hc, h = idx - il*Hc;
        cp[il*HPAD + h] = g_v[((0*Bc + b)*Lc + rl0[il])*Hc + h];
    }
    __syncthreads();

    int g = tid >> 5, lane = tid & 31;
    bool act0 = (r0c + g) < cnt1;
    bool act1 = (r0c + g) < cnt2;
    int i0r = rl0[g], i1r = rl1[g];

    if (act0) {
        float rni = g_rnorm[(0*Bc + b)*Lc + i0r];
        float vmax = MINV, fsum = 0.f;
        for (int jj = 0; jj < 4; jj++) {
            int j = jj*32 + lane;
            float a0=0.f, a1=0.f, a2=0.f, a3=0.f;
            #pragma unroll
            for (int h = 0; h < Hc; h += 4) {
                a0 += cp[g*HPAD + h+0] * ch[j*HPAD + h+0];
                a1 += cp[g*HPAD + h+1] * ch[j*HPAD + h+1];
                a2 += cp[g*HPAD + h+2] * ch[j*HPAD + h+2];
                a3 += cp[g*HPAD + h+3] * ch[j*HPAD + h+3];
            }
            float dot = (a0+a1)+(a2+a3);
            float c = dot * rni * rnh[j];
            g_cos[(b*Lc + i0r)*Lc + j] = c;
            cs[j*9 + g] = c;
            fsum += c;
            vmax = fmaxf(vmax, c + negj[j]);
        }
        #pragma unroll
        for (int o = 16; o; o >>= 1) {
            vmax = fmaxf(vmax, __shfl_xor_sync(0xffffffffu, vmax, o));
            fsum += __shfl_xor_sync(0xffffffffu, fsum, o);
        }
        if (lane == 0) {
            g_cmax[b*Lc + i0r]  = vmax;
            g_cmsum[b*Lc + i0r] = fsum;
            g_cfsum[b*Lc + i0r] = fsum;
        }
    }
    __syncthreads();
    if (tid < Lc) {
        int j = tid;
        #pragma unroll
        for (int gg = 0; gg < 8; gg++)
            if (r0c + gg < cnt1)
                g_cosT[(b*Lc + j)*Lc + rl0[gg]] = cs[j*9 + gg];
    }

    if (lane < 21) {
        float sab0=0.f, saa0=0.f, sbb0=0.f;
        float sab1=0.f, saa1=0.f, sbb1=0.f;
        #pragma unroll 4
        for (int h = 0; h < Hc; h++) {
            float w = (lane < 20) ? w0s[h*21 + lane] : 1.f;
            float a0 = cp[g*HPAD + h],  b0 = lasth[h];
            float a1 = ch[i1r*HPAD + h], b1 = lastp[h];
            sab0 = fmaf(w, a0*b0, sab0); saa0 = fmaf(w, a0*a0, saa0); sbb0 = fmaf(w, b0*b0, sbb0);
            sab1 = fmaf(w, a1*b1, sab1); saa1 = fmaf(w, a1*a1, saa1); sbb1 = fmaf(w, b1*b1, sbb1);
        }
        int col = (lane < 20) ? 3 + lane : 2;
        if (act0)
            out[(size_t)(b*Lc + i0r)*NCOL + col] =
                sab0 / (fmaxf(sqrtf(saa0), EPSF) * fmaxf(sqrtf(sbb0), EPSF));
        if (act1)
            out[(size_t)(Bc*Lc*NCOL) + (size_t)(b*Lc + i1r)*NCOL + col] =
                sab1 / (fmaxf(sqrtf(saa1), EPSF) * fmaxf(sqrtf(sbb1), EPSF));
    }
}

// ---------------- K3 fused v4: 8 rows/block, 256 threads, ~26 KB smem ----------------
__global__ __launch_bounds__(256) void k3_fused(const float* __restrict__ w2,
                                                const float* __restrict__ w3,
                                                float* __restrict__ out) {
    extern __shared__ float smf[];
    float* coef  = smf;                    // [8][128]
    float* coefc = coef + 8*Lc;            // [8][128] (tail zeroed)
    float* wsq   = coefc + 8*Lc;           // [2][100][20]
    float* amn   = wsq + 2*Hc*Pc;          // [8][HPAD]
    float* amx   = amn + 8*HPAD;           // [8][HPAD]
    float* v1r   = amx + 8*HPAD;           // [8][HPAD]
    float* fs8   = v1r + 8*HPAD;           // [8]
    float* cm8   = fs8 + 8;                // [8]
    int*   klist = (int*)(cm8 + 8);        // [128]
    int*   rlist = klist + Lc;             // [8]

    int b = blockIdx.x, s = blockIdx.z, o = 1 - s;
    int cntr = g_icnt[s*Bc + b];
    int r0c = blockIdx.y * 8;
    if (r0c >= cntr) return;
    int cntk = g_icnt[o*Bc + b];
    int tid = threadIdx.x;

    if (tid < 8) {
        int rc = r0c + tid;
        rlist[tid] = g_ilist[(s*Bc + b)*Lc + ((rc < cntr) ? rc : cntr - 1)];
    }
    if (tid >= 128 && tid < 256) {
        int t2 = tid - 128;
        klist[t2] = (t2 < cntk) ? g_ilist[(o*Bc + b)*Lc + t2] : 0;
    }
    for (int idx = tid; idx < 2*Hc*Pc; idx += 256) {
        int pr = idx / (Hc*Pc);
        int r2i = idx - pr*(Hc*Pc);
        int h = r2i / Pc, p = r2i - h*Pc;
        const float* w = (pr == 0) ? w2 : w3;
        float wv = w[p*Hc + h];
        wsq[pr*Hc*Pc + h*Pc + p] = wv*wv;
    }
    __syncthreads();

    const float* src = (s == 0) ? g_cos : g_cosT;
    for (int idx = tid; idx < 8*Lc; idx += 256) {
        int rl = idx >> 7, col = idx & 127;
        coef[rl*Lc + col] = src[(b*Lc + rlist[rl])*Lc + col];
    }
    for (int idx = tid; idx < 8*Hc; idx += 256) {
        int il = idx / Hc, h = idx - il*Hc;
        v1r[il*HPAD + h] = g_v[((size_t)(s*Bc + b)*Lc + rlist[il])*Hc + h];
    }
    __syncthreads();

    int half = tid >> 7, ht = tid & 127;

    // gather compacted coefficients: half 0 rows 0-3, half 1 rows 4-7; zero tail
    if (ht < cntk) {
        int k = klist[ht];
        #pragma unroll
        for (int rl = 0; rl < 4; rl++)
            coefc[(half*4 + rl)*Lc + ht] = coef[(half*4 + rl)*Lc + k];
    } else {
        #pragma unroll
        for (int rl = 0; rl < 4; rl++)
            coefc[(half*4 + rl)*Lc + ht] = 0.f;
    }
    __syncthreads();

    // s==1: stats from coefc (one row per warp; fs == masked sum: masked cos entries are 0)
    if (s == 1) {
        int w = tid >> 5, lane = tid & 31;   // warp w handles row w (0-7)
        float v0 = coefc[w*Lc + lane],    v1 = coefc[w*Lc + lane+32];
        float v2 = coefc[w*Lc + lane+64], v3 = coefc[w*Lc + lane+96];
        float fs = (v0+v1) + (v2+v3);
        float vm = fmaxf(fmaxf((lane    < cntk) ? v0 : MINV,
                               (lane+32 < cntk) ? v1 : MINV),
                         fmaxf((lane+64 < cntk) ? v2 : MINV,
                               (lane+96 < cntk) ? v3 : MINV));
        #pragma unroll
        for (int o2 = 16; o2; o2 >>= 1) {
            fs += __shfl_xor_sync(0xffffffffu, fs, o2);
            vm = fmaxf(vm, __shfl_xor_sync(0xffffffffu, vm, o2));
        }
        if (lane == 0) { fs8[w] = fs; cm8[w] = vm; }
        __syncthreads();
    }

    // attentive mean/max vectors -> smem (half 0: rows 0-3, half 1: rows 4-7)
    if (ht < Hc) {
        float acc[4], axv[4];
        #pragma unroll
        for (int rl = 0; rl < 4; rl++) { acc[rl] = 0.f; axv[rl] = MINV; }
        const float* vcbase = &g_vc[((size_t)(o*Bc + b)*Lc)*Hc + ht];
        #pragma unroll 4
        for (int kk = 0; kk < cntk; kk++) {
            float pv = __ldg(vcbase + kk*Hc);
            #pragma unroll
            for (int rl = 0; rl < 4; rl++) {
                float prod = coefc[(half*4 + rl)*Lc + kk] * pv;
                acc[rl] += prod;
                axv[rl] = fmaxf(axv[rl], prod);
            }
        }
        float maxm2 = g_maxm[o*Bc + b];
        #pragma unroll
        for (int rl = 0; rl < 4; rl++) {
            int lr = half*4 + rl;
            float fs = (s == 1) ? fs8[lr] : g_cfsum[b*Lc + rlist[lr]];
            amn[lr*HPAD + ht] = __fdividef(acc[rl], fmaxf(fs, EPSF));
            amx[lr*HPAD + ht] = axv[rl] * maxm2;
        }
    }
    __syncthreads();

    // ---- task loop: 8 rows x 21 slots = 168 tasks, single pass ----
    float cnt2  = g_cnt[o*Bc + b];
    float maxm2 = g_maxm[o*Bc + b];
    if (tid < 168) {
        int il = tid & 7, q = tid >> 3;
        if (r0c + il < cntr) {
            int i = rlist[il];
            float* orow = out + (size_t)s*(Bc*Lc*NCOL) + (size_t)(b*Lc + i)*NCOL;

            if (q == 0) {
                float cm = (s == 0) ? g_cmax [b*Lc + i] : cm8[il];
                float cv = (s == 0) ? g_cmsum[b*Lc + i] : fs8[il];
                orow[0] = cm * maxm2;
                orow[1] = cv / fmaxf(cnt2, EPSF);
            }

            float sab[2] = {0.f,0.f}, saa[2] = {0.f,0.f}, sbb[2] = {0.f,0.f};
            if (q == 0) {
                #pragma unroll 4
                for (int h = 0; h < Hc; h++) {
                    float a  = v1r[il*HPAD + h];
                    float b1 = amn[il*HPAD + h], b2 = amx[il*HPAD + h];
                    float aa = a*a;
                    sab[0] = fmaf(a, b1, sab[0]); sbb[0] = fmaf(b1, b1, sbb[0]);
                    sab[1] = fmaf(a, b2, sab[1]); sbb[1] = fmaf(b2, b2, sbb[1]);
                    saa[0] += aa;
                }
                saa[1] = saa[0];
            } else {
                int p = q - 1;
                #pragma unroll 2
                for (int h = 0; h < Hc; h++) {
                    float a  = v1r[il*HPAD + h];
                    float b1 = amn[il*HPAD + h], b2 = amx[il*HPAD + h];
                    float w1v = wsq[h*Pc + p], w2v = wsq[Hc*Pc + h*Pc + p];
                    float aa = a*a;
                    sab[0] = fmaf(w1v, a*b1, sab[0]); saa[0] = fmaf(w1v, aa, saa[0]); sbb[0] = fmaf(w1v, b1*b1, sbb[0]);
                    sab[1] = fmaf(w2v, a*b2, sab[1]); saa[1] = fmaf(w2v, aa, saa[1]); sbb[1] = fmaf(w2v, b2*b2, sbb[1]);
                }
            }
            #pragma unroll
            for (int pr = 0; pr < 2; pr++) {
                float val = sab[pr] / (fmaxf(sqrtf(saa[pr]), EPSF) * fmaxf(sqrtf(sbb[pr]), EPSF));
                int col = (pr == 0) ? ((q == 0) ? 63 : 64 + (q - 1))
                        :             ((q == 0) ? 84 : 85 + (q - 1));
                orow[col] = val;
            }
        }
    }
}

// ---------------- K4: mask-compacted symmetric pairwise GEMM ----------------
__global__ __launch_bounds__(256, 3) void k4_sym(const float* __restrict__ w1,
                                                 float* __restrict__ out) {
    __shared__ float wsq[Hc];
    __shared__ int ilist[Lc], jlist[Lc];
    __shared__ float rnw1c[Lc], rnw2c[Lc];
    __shared__ float rowmax_s[Lc], rowsum_s[Lc], colmax_s[Lc], colsum_s[Lc];
    __shared__ __align__(16) float aT[50*PAD84];
    __shared__ __align__(16) float bT[50*PAD84];

    int b = blockIdx.x, p = blockIdx.y;
    int tid = threadIdx.x;
    int tx = tid & 15, ty = tid >> 4;
    int cnt1 = g_icnt[b], cnt2 = g_icnt[Bc + b];

    for (int idx = tid; idx < Hc; idx += 256) {
        float w = __ldg(&w1[p*Hc + idx]);
        wsq[idx] = w*w;
    }
    if (tid < Lc) {
        ilist[tid] = (tid < cnt1) ? g_ilist[b*Lc + tid] : 0;
        jlist[tid] = (tid < cnt2) ? g_ilist[(Bc + b)*Lc + tid] : 0;
        rowmax_s[tid] = MINV; rowsum_s[tid] = 0.f;
        colmax_s[tid] = MINV; colsum_s[tid] = 0.f;
    }
    __syncthreads();
    if (tid < Lc) {
        rnw1c[tid] = (tid < cnt1) ? g_rnw[(b*Lc + ilist[tid])*Pc + p] : 0.f;
        rnw2c[tid] = (tid < cnt2) ? g_rnw[((Bc + b)*Lc + jlist[tid])*Pc + p] : 0.f;
    }

    const float* vc0 = &g_vc[(size_t)(0*Bc + b)*Lc*Hc];
    const float* vc1 = &g_vc[(size_t)(1*Bc + b)*Lc*Hc];

    int npi = (cnt1 + 79) / 80;
    int npj = (cnt2 + 79) / 80;

    for (int pi = 0; pi < npi; pi++)
    for (int pj = 0; pj < npj; pj++) {
        float acc[5][5];
        #pragma unroll
        for (int r = 0; r < 5; r++)
            #pragma unroll
            for (int c = 0; c < 5; c++) acc[r][c] = 0.f;

        #pragma unroll 1
        for (int kc = 0; kc < 2; kc++) {
            __syncthreads();
            for (int idx = tid; idx < 50*80; idx += 256) {
                int kk = idx / 80, ii = idx - kk*80;
                int k = kc*50 + kk;
                int ic = pi*80 + ii;
                int jc = pj*80 + ii;
                aT[kk*PAD84 + ii] = (ic < cnt1 && k < Hc) ? wsq[k] * vc0[(size_t)ic*Hc + k] : 0.f;
                bT[kk*PAD84 + ii] = (jc < cnt2 && k < Hc) ? vc1[(size_t)jc*Hc + k] : 0.f;
            }
            __syncthreads();
            #pragma unroll 5
            for (int kk = 0; kk < 50; kk++) {
                float av[5], bv[5];
                #pragma unroll
                for (int r = 0; r < 5; r++) av[r] = aT[kk*PAD84 + r*16 + ty];
                #pragma unroll
                for (int c = 0; c < 5; c++) bv[c] = bT[kk*PAD84 + c*16 + tx];
                #pragma unroll
                for (int r = 0; r < 5; r++)
                    #pragma unroll
                    for (int c = 0; c < 5; c++)
                        acc[r][c] = fmaf(av[r], bv[c], acc[r][c]);
            }
        }

        float rowm[5], rows_[5], colm[5], cols_[5];
        #pragma unroll
        for (int r = 0; r < 5; r++) { rowm[r] = MINV; rows_[r] = 0.f; colm[r] = MINV; cols_[r] = 0.f; }
        #pragma unroll
        for (int r = 0; r < 5; r++) {
            int ic = pi*80 + r*16 + ty;
            bool vi = ic < cnt1;
            float r1 = vi ? rnw1c[vi ? ic : 0] : 0.f;
            float negi_ = vi ? 0.f : MINV;
            #pragma unroll
            for (int c = 0; c < 5; c++) {
                int jc = pj*80 + c*16 + tx;
                bool vj = jc < cnt2;
                float r2 = vj ? rnw2c[vj ? jc : 0] : 0.f;
                float val = acc[r][c] * r1 * r2;
                rowm[r] = fmaxf(rowm[r], val + (vj ? 0.f : MINV));
                rows_[r] += val;
                colm[c] = fmaxf(colm[c], val + negi_);
                cols_[c] += val;
            }
        }
        __syncthreads();
        #pragma unroll
        for (int r = 0; r < 5; r++) {
            int i80 = r*16 + ty;
            aT[i80*17 + tx] = rowm[r];
            bT[i80*17 + tx] = rows_[r];
        }
        __syncthreads();
        if (tid < 80) {
            int ic = pi*80 + tid;
            if (ic < cnt1) {
                float vm = MINV, vs = 0.f;
                #pragma unroll
                for (int t = 0; t < 16; t++) { vm = fmaxf(vm, aT[tid*17 + t]); vs += bT[tid*17 + t]; }
                rowmax_s[ic] = fmaxf(rowmax_s[ic], vm);
                rowsum_s[ic] += vs;
            }
        }
        __syncthreads();
        #pragma unroll
        for (int c = 0; c < 5; c++) {
            int j80 = c*16 + tx;
            aT[j80*17 + ty] = colm[c];
            bT[j80*17 + ty] = cols_[c];
        }
        __syncthreads();
        if (tid < 80) {
            int jc = pj*80 + tid;
            if (jc < cnt2) {
                float vm = MINV, vs = 0.f;
                #pragma unroll
                for (int t = 0; t < 16; t++) { vm = fmaxf(vm, aT[tid*17 + t]); vs += bT[tid*17 + t]; }
                colmax_s[jc] = fmaxf(colmax_s[jc], vm);
                colsum_s[jc] += vs;
            }
        }
        __syncthreads();
    }

    if (tid < cnt1) {
        int i = ilist[tid];
        float mm2 = g_maxm[Bc + b];
        float c2  = g_cnt[Bc + b];
        float* orow = out + (size_t)(b*Lc + i)*NCOL;
        orow[23 + p] = rowmax_s[tid] * mm2;
        orow[43 + p] = rowsum_s[tid] / fmaxf(c2, EPSF);
    }
    if (tid < cnt2) {
        int j = jlist[tid];
        float mm1 = g_maxm[b];
        float c1  = g_cnt[b];
        float* orow = out + (size_t)(Bc*Lc*NCOL) + (size_t)(b*Lc + j)*NCOL;
        orow[23 + p] = colmax_s[tid] * mm1;
        orow[43 + p] = colsum_s[tid] / fmaxf(c1, EPSF);
    }
}

// ---------------- launch (two streams: k4 overlaps k1+k3fused) ----------------
extern "C" void kernel_launch(void* const* d_in, const int* in_sizes, int n_in,
                              void* d_out, int out_size) {
    const float* ctxp  = (const float*)d_in[0];
    const int*   maskp = (const int*)  d_in[1];
    const float* ctxh  = (const float*)d_in[2];
    const int*   maskh = (const int*)  d_in[3];
    const float* w0    = (const float*)d_in[4];
    const float* w1    = (const float*)d_in[5];
    const float* w2    = (const float*)d_in[6];
    const float* w3    = (const float*)d_in[7];
    float* out = (float*)d_out;

    static cudaStream_t s2 = [](){ cudaStream_t s; cudaStreamCreateWithFlags(&s, cudaStreamNonBlocking); return s; }();
    static cudaEvent_t evF = [](){ cudaEvent_t e; cudaEventCreateWithFlags(&e, cudaEventDisableTiming); return e; }();
    static cudaEvent_t evJ = [](){ cudaEvent_t e; cudaEventCreateWithFlags(&e, cudaEventDisableTiming); return e; }();

    const int SM0 = (Lc*HPAD + Hc*Pc + Lc) * 4;
    const int SM1 = (Lc*HPAD + 2*Lc + 8*HPAD + Lc*9 + 104 + 104 + Hc*21) * 4;
    const int SM3 = (8*Lc*2 + 2*Hc*Pc + 3*8*HPAD + 16) * 4 + (Lc + 8) * 4;   // ~26.5 KB
    cudaFuncSetAttribute(k0_prep,  cudaFuncAttributeMaxDynamicSharedMemorySize, SM0);
    cudaFuncSetAttribute(k1_cos,   cudaFuncAttributeMaxDynamicSharedMemorySize, SM1);
    cudaFuncSetAttribute(k3_fused, cudaFuncAttributeMaxDynamicSharedMemorySize, SM3);

    k0_prep<<<dim3(Bc, 2), 256, SM0>>>(ctxp, maskp, ctxh, maskh, w1, out);

    cudaEventRecord(evF, 0);
    cudaStreamWaitEvent(s2, evF, 0);
    k4_sym<<<dim3(Bc, Pc), 256, 0, s2>>>(w1, out);
    cudaEventRecord(evJ, s2);

    k1_cos<<<dim3(Bc, 16), 256, SM1>>>(w0, out);
    k3_fused<<<dim3(Bc, 16, 2), 256, SM3>>>(w2, w3, out);

    cudaStreamWaitEvent(0, evJ, 0);
}